// round 3
// baseline (speedup 1.0000x reference)
#include <cuda_runtime.h>
#include <cstddef>

#define SEQ    2048
#define DMODEL 1024
#define DKEY   64
#define NBATCH 8
#define ROWS   (NBATCH * SEQ)   // 16384 tokens

// ---------------- scratch (device globals; no runtime allocation) ----------------
__device__ float g_q[(size_t)NBATCH * SEQ * DKEY];            //  4 MB
__device__ float g_k[(size_t)NBATCH * SEQ * DKEY];            //  4 MB
__device__ float g_v[(size_t)NBATCH * SEQ * DMODEL];          // 64 MB
__device__ float g_p[(size_t)NBATCH * SEQ * SEQ];             // 134 MB

// =================================================================================
// Generic tiled SGEMM body:  C[M,N] = A[M,K] @ W[K,N] + bias[N]
// A row-major, W row-major. M%BM==0, N%BN==0, K%BK==0 guaranteed by caller.
// =================================================================================
template<int BM, int BN, int BK, int TM, int TN>
__device__ __forceinline__ void gemm_bias_body(
    const float* __restrict__ A, const float* __restrict__ W,
    const float* __restrict__ bias, float* __restrict__ C,
    int M, int N, int K)
{
    constexpr int THREADS = (BM / TM) * (BN / TN);   // 256 in both configs
    __shared__ float As[BK][BM];
    __shared__ float Bs[BK][BN];

    const int tid   = threadIdx.x;
    const int tcols = BN / TN;
    const int trow  = tid / tcols;
    const int tcol  = tid % tcols;
    const int rowBase = blockIdx.y * BM;
    const int colBase = blockIdx.x * BN;

    float acc[TM][TN];
#pragma unroll
    for (int i = 0; i < TM; i++)
#pragma unroll
        for (int j = 0; j < TN; j++) acc[i][j] = 0.0f;

    for (int k0 = 0; k0 < K; k0 += BK) {
        // ---- load A tile (BM x BK), store transposed As[k][m] ----
        constexpr int AV = (BM * BK) / (THREADS * 4);
#pragma unroll
        for (int i = 0; i < AV; i++) {
            int idx = (tid + i * THREADS) * 4;
            int m   = idx / BK;
            int kk  = idx % BK;
            float4 v = *(const float4*)&A[(size_t)(rowBase + m) * K + k0 + kk];
            As[kk + 0][m] = v.x; As[kk + 1][m] = v.y;
            As[kk + 2][m] = v.z; As[kk + 3][m] = v.w;
        }
        // ---- load W tile (BK x BN) ----
        constexpr int BV = (BK * BN) / (THREADS * 4);
#pragma unroll
        for (int i = 0; i < BV; i++) {
            int idx = (tid + i * THREADS) * 4;
            int kk  = idx / BN;
            int n   = idx % BN;
            *(float4*)&Bs[kk][n] =
                *(const float4*)&W[(size_t)(k0 + kk) * N + colBase + n];
        }
        __syncthreads();

#pragma unroll
        for (int kk = 0; kk < BK; kk++) {
            float a[TM], b[TN];
#pragma unroll
            for (int i = 0; i < TM; i++) a[i] = As[kk][trow * TM + i];
#pragma unroll
            for (int j = 0; j < TN; j++) b[j] = Bs[kk][tcol * TN + j];
#pragma unroll
            for (int i = 0; i < TM; i++)
#pragma unroll
                for (int j = 0; j < TN; j++) acc[i][j] += a[i] * b[j];
        }
        __syncthreads();
    }

#pragma unroll
    for (int i = 0; i < TM; i++) {
        int m = rowBase + trow * TM + i;
#pragma unroll
        for (int j = 0; j < TN; j++) {
            int n = colBase + tcol * TN + j;
            C[(size_t)m * N + n] = acc[i][j] + bias[n];
        }
    }
}

// Projection kernels (thin wrappers binding the scratch globals)
__global__ __launch_bounds__(256) void proj_q_kernel(
    const float* __restrict__ x, const float* __restrict__ Wq, const float* __restrict__ bq) {
    gemm_bias_body<128, 64, 16, 8, 4>(x, Wq, bq, g_q, ROWS, DKEY, DMODEL);
}
__global__ __launch_bounds__(256) void proj_k_kernel(
    const float* __restrict__ x, const float* __restrict__ Wk, const float* __restrict__ bk) {
    gemm_bias_body<128, 64, 16, 8, 4>(x, Wk, bk, g_k, ROWS, DKEY, DMODEL);
}
__global__ __launch_bounds__(256) void proj_v_kernel(
    const float* __restrict__ x, const float* __restrict__ Wv, const float* __restrict__ bv) {
    gemm_bias_body<128, 128, 16, 8, 8>(x, Wv, bv, g_v, ROWS, DMODEL, DMODEL);
}

// =================================================================================
// scores[b,i,j] = (q[b,i,:] . k[b,j,:]) / 8  — batched NT GEMM, lower-tri tiles only
// 128x128 output tile per CTA, K=64 split in two 32-chunks (smem 32 KB).
// =================================================================================
__global__ __launch_bounds__(256) void scores_kernel() {
    const int tj = blockIdx.x;      // key   tile
    const int ti = blockIdx.y;      // query tile
    if (tj > ti) return;            // strictly above diagonal: never read downstream
    const int b  = blockIdx.z;

    __shared__ float Qs[32][128];
    __shared__ float Ks[32][128];

    const int tid  = threadIdx.x;
    const int trow = tid / 16;
    const int tcol = tid % 16;

    const float* q = g_q + (size_t)b * SEQ * DKEY + (size_t)ti * 128 * DKEY;
    const float* k = g_k + (size_t)b * SEQ * DKEY + (size_t)tj * 128 * DKEY;

    float acc[8][8];
#pragma unroll
    for (int i = 0; i < 8; i++)
#pragma unroll
        for (int j = 0; j < 8; j++) acc[i][j] = 0.0f;

    for (int kc = 0; kc < DKEY; kc += 32) {
#pragma unroll
        for (int i = 0; i < 4; i++) {
            int idx = (tid + i * 256) * 4;
            int m   = idx / 32;
            int kk  = idx % 32;
            float4 vq = *(const float4*)&q[m * DKEY + kc + kk];
            Qs[kk + 0][m] = vq.x; Qs[kk + 1][m] = vq.y;
            Qs[kk + 2][m] = vq.z; Qs[kk + 3][m] = vq.w;
            float4 vk = *(const float4*)&k[m * DKEY + kc + kk];
            Ks[kk + 0][m] = vk.x; Ks[kk + 1][m] = vk.y;
            Ks[kk + 2][m] = vk.z; Ks[kk + 3][m] = vk.w;
        }
        __syncthreads();
#pragma unroll
        for (int kk = 0; kk < 32; kk++) {
            float a[8], bb[8];
#pragma unroll
            for (int i = 0; i < 8; i++) a[i]  = Qs[kk][trow * 8 + i];
#pragma unroll
            for (int j = 0; j < 8; j++) bb[j] = Ks[kk][tcol * 8 + j];
#pragma unroll
            for (int i = 0; i < 8; i++)
#pragma unroll
                for (int j = 0; j < 8; j++) acc[i][j] += a[i] * bb[j];
        }
        __syncthreads();
    }

    const float scale = 0.125f;  // 1/sqrt(64)
    float* p = g_p + (size_t)b * SEQ * SEQ;
#pragma unroll
    for (int i = 0; i < 8; i++) {
        int qi = ti * 128 + trow * 8 + i;
#pragma unroll
        for (int j = 0; j < 8; j++) {
            int kj = tj * 128 + tcol * 8 + j;
            // masked (kj>qi) entries of the diagonal tile are overwritten by softmax
            p[(size_t)qi * SEQ + kj] = acc[i][j] * scale;
        }
    }
}

// =================================================================================
// Row-wise causal softmax over g_p. One CTA per (b,i) row; row cached in smem.
// Writes normalized probs for j<=i and ZEROS for j in (i, round_up(i+1,128)) so
// the PV GEMM can consume whole 128-wide K-tiles.
// =================================================================================
__global__ __launch_bounds__(256) void softmax_kernel() {
    const int row = blockIdx.x;          // 0 .. B*SEQ-1
    const int b   = row / SEQ;
    const int i   = row % SEQ;
    float* p = g_p + (size_t)b * SEQ * SEQ + (size_t)i * SEQ;

    const int L  = i + 1;
    const int Lp = ((i + 1 + 127) / 128) * 128;

    __shared__ float buf[SEQ];           // 8 KB
    __shared__ float red[256];
    const int tid = threadIdx.x;

    float mx = -3.4e38f;
    for (int j = tid; j < L; j += 256) {
        float v = p[j];
        buf[j] = v;
        mx = fmaxf(mx, v);
    }
    red[tid] = mx;
    __syncthreads();
    for (int s = 128; s > 0; s >>= 1) {
        if (tid < s) red[tid] = fmaxf(red[tid], red[tid + s]);
        __syncthreads();
    }
    mx = red[0];
    __syncthreads();

    float sum = 0.0f;
    for (int j = tid; j < L; j += 256) {
        float e = __expf(buf[j] - mx);
        buf[j] = e;
        sum += e;
    }
    red[tid] = sum;
    __syncthreads();
    for (int s = 128; s > 0; s >>= 1) {
        if (tid < s) red[tid] += red[tid + s];
        __syncthreads();
    }
    const float inv = 1.0f / red[0];

    for (int j = tid; j < Lp; j += 256)
        p[j] = (j < L) ? buf[j] * inv : 0.0f;
}

// =================================================================================
// O[b] = P[b] @ V[b]  — batched 128x128x16 SGEMM with causal K bound
// For q-tile starting at rowBase, K runs only to kmax = rowBase+128 (halves work).
// =================================================================================
__global__ __launch_bounds__(256) void pv_kernel(float* __restrict__ O) {
    const int b       = blockIdx.z;
    const int rowBase = blockIdx.y * 128;
    const int colBase = blockIdx.x * 128;
    const int kmax    = rowBase + 128;

    const float* p = g_p + (size_t)b * SEQ * SEQ;
    const float* v = g_v + (size_t)b * SEQ * DMODEL;
    float*       o = O   + (size_t)b * SEQ * DMODEL;

    __shared__ float As[16][128];
    __shared__ float Bs[16][128];

    const int tid  = threadIdx.x;
    const int trow = tid / 16;
    const int tcol = tid % 16;

    float acc[8][8];
#pragma unroll
    for (int i = 0; i < 8; i++)
#pragma unroll
        for (int j = 0; j < 8; j++) acc[i][j] = 0.0f;

    for (int k0 = 0; k0 < kmax; k0 += 16) {
#pragma unroll
        for (int i = 0; i < 2; i++) {
            int idx = (tid + i * 256) * 4;
            int m   = idx / 16;
            int kk  = idx % 16;
            float4 va = *(const float4*)&p[(size_t)(rowBase + m) * SEQ + k0 + kk];
            As[kk + 0][m] = va.x; As[kk + 1][m] = va.y;
            As[kk + 2][m] = va.z; As[kk + 3][m] = va.w;

            int kb = idx / 128;
            int n  = idx % 128;
            *(float4*)&Bs[kb][n] =
                *(const float4*)&v[(size_t)(k0 + kb) * DMODEL + colBase + n];
        }
        __syncthreads();
#pragma unroll
        for (int kk = 0; kk < 16; kk++) {
            float a[8], bb[8];
#pragma unroll
            for (int i = 0; i < 8; i++) a[i]  = As[kk][trow * 8 + i];
#pragma unroll
            for (int j = 0; j < 8; j++) bb[j] = Bs[kk][tcol * 8 + j];
#pragma unroll
            for (int i = 0; i < 8; i++)
#pragma unroll
                for (int j = 0; j < 8; j++) acc[i][j] += a[i] * bb[j];
        }
        __syncthreads();
    }

#pragma unroll
    for (int i = 0; i < 8; i++) {
        int m = rowBase + trow * 8 + i;
#pragma unroll
        for (int j = 0; j < 8; j++) {
            int n = colBase + tcol * 8 + j;
            o[(size_t)m * DMODEL + n] = acc[i][j];
        }
    }
}

// =================================================================================
// Launch: 6 graph-capturable kernel launches, no allocs, no syncs.
// Input order (metadata): input, Wq, bq, Wk, bk, Wv, bv
// =================================================================================
extern "C" void kernel_launch(void* const* d_in, const int* in_sizes, int n_in,
                              void* d_out, int out_size)
{
    const float* x  = (const float*)d_in[0];
    const float* Wq = (const float*)d_in[1];
    const float* bq = (const float*)d_in[2];
    const float* Wk = (const float*)d_in[3];
    const float* bk = (const float*)d_in[4];
    const float* Wv = (const float*)d_in[5];
    const float* bv = (const float*)d_in[6];
    float* out = (float*)d_out;

    // Projections
    proj_q_kernel<<<dim3(DKEY / 64,    ROWS / 128), 256>>>(x, Wq, bq);
    proj_k_kernel<<<dim3(DKEY / 64,    ROWS / 128), 256>>>(x, Wk, bk);
    proj_v_kernel<<<dim3(DMODEL / 128, ROWS / 128), 256>>>(x, Wv, bv);

    // Scores (lower-triangular tiles only)
    scores_kernel<<<dim3(SEQ / 128, SEQ / 128, NBATCH), 256>>>();

    // Row softmax
    softmax_kernel<<<NBATCH * SEQ, 256>>>();

    // P @ V with causal K bound
    pv_kernel<<<dim3(DMODEL / 128, SEQ / 128, NBATCH), 256>>>(out);
}

// round 5
// speedup vs baseline: 2.8247x; 2.8247x over previous
#include <cuda_runtime.h>
#include <cstdint>
#include <cstddef>

#define SEQ    2048
#define DMODEL 1024
#define DKEY   64
#define NBATCH 8
#define ROWS   (NBATCH * SEQ)   // 16384 tokens

// ---------------- scratch (device globals; no runtime allocation) ----------------
__device__ __align__(256) float g_q[(size_t)NBATCH * SEQ * DKEY];     //  4 MB
__device__ __align__(256) float g_k[(size_t)NBATCH * SEQ * DKEY];     //  4 MB
__device__ __align__(256) float g_v[(size_t)NBATCH * SEQ * DMODEL];   // 64 MB
__device__ __align__(256) float g_p[(size_t)NBATCH * SEQ * SEQ];      // 134 MB

// ---------------- tf32 mma primitives ----------------
__device__ __forceinline__ uint32_t cvt_tf32(float x) {
    uint32_t r;
    asm("cvt.rna.tf32.f32 %0, %1;" : "=r"(r) : "f"(x));
    return r;
}

__device__ __forceinline__ void ldsm4(uint32_t addr, uint32_t& r0, uint32_t& r1,
                                      uint32_t& r2, uint32_t& r3) {
    asm volatile("ldmatrix.sync.aligned.m8n8.x4.shared.b16 {%0,%1,%2,%3}, [%4];"
                 : "=r"(r0), "=r"(r1), "=r"(r2), "=r"(r3) : "r"(addr));
}

__device__ __forceinline__ void mma8(float* c, const uint32_t* a, uint32_t b0, uint32_t b1) {
    asm volatile(
        "mma.sync.aligned.m16n8k8.row.col.f32.tf32.tf32.f32 "
        "{%0,%1,%2,%3}, {%4,%5,%6,%7}, {%8,%9}, {%0,%1,%2,%3};"
        : "+f"(c[0]), "+f"(c[1]), "+f"(c[2]), "+f"(c[3])
        : "r"(a[0]), "r"(a[1]), "r"(a[2]), "r"(a[3]), "r"(b0), "r"(b1));
}

// =================================================================================
// Generic tf32 tensor-core GEMM body:  C[.,.] = scale * A@B (+bias)
//   A: [M,K] row-major (lda).   B: if BNK, B is [N,K] row-major (C = A @ B^T);
//   else B is [K,N] row-major (C = A @ B).  BK=32 fixed (8 16B-chunks per smem row,
//   XOR-swizzled chunk ^= row&7 for conflict-free ldmatrix).
// =================================================================================
template<int BM, int BN, int WR, int WC, bool BNK>
__device__ __forceinline__ void mma_gemm(
    const float* __restrict__ A, int lda,
    const float* __restrict__ B, int ldb,
    float* __restrict__ C, int ldc,
    int K, const float* __restrict__ bias, float scale,
    int rowBase, int colBase)
{
    constexpr int BK  = 32;
    constexpr int ACH = BK / 4;            // 8 chunks of 16B per row
    constexpr int WM  = BM / WR;
    constexpr int WN  = BN / WC;
    constexpr int MT  = WM / 16;
    constexpr int NT  = WN / 8;
    constexpr int NP  = NT / 2;

    __shared__ float As[BM * BK];
    __shared__ float Bs[BN * BK];

    const int tid  = threadIdx.x;
    const int lane = tid & 31;
    const int warp = tid >> 5;
    const int wr   = warp / WC;
    const int wc   = warp % WC;

    const uint32_t sA = (uint32_t)__cvta_generic_to_shared(As);
    const uint32_t sB = (uint32_t)__cvta_generic_to_shared(Bs);

    float acc[MT][NT][4] = {};

    for (int k0 = 0; k0 < K; k0 += BK) {
        // ---- A tile: straight float4 copy, cvt to tf32, swizzled STS.128 ----
#pragma unroll
        for (int s = 0; s < BM * ACH / 256; s++) {
            int lin = tid + s * 256;
            int m = lin / ACH, c = lin % ACH;
            float4 v = *(const float4*)&A[(size_t)(rowBase + m) * lda + k0 + c * 4];
            uint4 t = make_uint4(cvt_tf32(v.x), cvt_tf32(v.y), cvt_tf32(v.z), cvt_tf32(v.w));
            *(uint4*)&As[m * BK + ((c ^ (m & 7)) << 2)] = t;
        }
        // ---- B tile -> Bs[n][k] ----
        if (BNK) {
            // B already [N,K]: straight copy
#pragma unroll
            for (int s = 0; s < BN * ACH / 256; s++) {
                int lin = tid + s * 256;
                int n = lin / ACH, c = lin % ACH;
                float4 v = *(const float4*)&B[(size_t)(colBase + n) * ldb + k0 + c * 4];
                uint4 t = make_uint4(cvt_tf32(v.x), cvt_tf32(v.y), cvt_tf32(v.z), cvt_tf32(v.w));
                *(uint4*)&Bs[n * BK + ((c ^ (n & 7)) << 2)] = t;
            }
        } else {
            // B is [K,N]: transpose on the fly (4 coalesced scalar LDG -> one STS.128)
#pragma unroll
            for (int s = 0; s < BN * ACH / 256; s++) {
                int lin = tid + s * 256;
                int n = lin % BN, kg = lin / BN;
                const float* src = &B[(size_t)(k0 + 4 * kg) * ldb + colBase + n];
                uint4 t = make_uint4(cvt_tf32(src[0]),
                                     cvt_tf32(src[(size_t)ldb]),
                                     cvt_tf32(src[(size_t)2 * ldb]),
                                     cvt_tf32(src[(size_t)3 * ldb]));
                *(uint4*)&Bs[n * BK + ((kg ^ (n & 7)) << 2)] = t;
            }
        }
        __syncthreads();

        // ---- compute: 4 k8-steps ----
#pragma unroll
        for (int kc = 0; kc < BK; kc += 8) {
            uint32_t a[MT][4];
#pragma unroll
            for (int mi = 0; mi < MT; mi++) {
                int m   = wr * WM + mi * 16 + (lane & 7) + ((lane >> 3) & 1) * 8;
                int kch = (kc >> 2) + ((lane >> 4) & 1);
                uint32_t addr = sA + (uint32_t)(m * BK + ((kch ^ (m & 7)) << 2)) * 4u;
                ldsm4(addr, a[mi][0], a[mi][1], a[mi][2], a[mi][3]);
            }
#pragma unroll
            for (int p = 0; p < NP; p++) {
                int n   = wc * WN + p * 16 + (lane & 7) + ((lane >> 4) & 1) * 8;
                int kch = (kc >> 2) + ((lane >> 3) & 1);
                uint32_t addr = sB + (uint32_t)(n * BK + ((kch ^ (n & 7)) << 2)) * 4u;
                uint32_t b0, b1, b2, b3;
                ldsm4(addr, b0, b1, b2, b3);
#pragma unroll
                for (int mi = 0; mi < MT; mi++) {
                    mma8(acc[mi][2 * p],     a[mi], b0, b1);
                    mma8(acc[mi][2 * p + 1], a[mi], b2, b3);
                }
            }
        }
        __syncthreads();
    }

    // ---- epilogue ----
    const int gid = lane >> 2, tig = lane & 3;
#pragma unroll
    for (int mi = 0; mi < MT; mi++) {
#pragma unroll
        for (int nt = 0; nt < NT; nt++) {
            int m = rowBase + wr * WM + mi * 16 + gid;
            int n = colBase + wc * WN + nt * 8 + 2 * tig;
            float bb0 = 0.f, bb1 = 0.f;
            if (bias) { bb0 = bias[n]; bb1 = bias[n + 1]; }
            float2 o0 = make_float2(acc[mi][nt][0] * scale + bb0,
                                    acc[mi][nt][1] * scale + bb1);
            *(float2*)&C[(size_t)m * ldc + n] = o0;
            float2 o1 = make_float2(acc[mi][nt][2] * scale + bb0,
                                    acc[mi][nt][3] * scale + bb1);
            *(float2*)&C[(size_t)(m + 8) * ldc + n] = o1;
        }
    }
}

// ---------------- kernel wrappers ----------------
__global__ __launch_bounds__(256) void proj_q_kernel(
    const float* __restrict__ x, const float* __restrict__ Wq, const float* __restrict__ bq) {
    mma_gemm<128, 64, 4, 2, false>(x, DMODEL, Wq, DKEY, g_q, DKEY,
                                   DMODEL, bq, 1.0f, blockIdx.y * 128, 0);
}
__global__ __launch_bounds__(256) void proj_k_kernel(
    const float* __restrict__ x, const float* __restrict__ Wk, const float* __restrict__ bk) {
    mma_gemm<128, 64, 4, 2, false>(x, DMODEL, Wk, DKEY, g_k, DKEY,
                                   DMODEL, bk, 1.0f, blockIdx.y * 128, 0);
}
__global__ __launch_bounds__(256) void proj_v_kernel(
    const float* __restrict__ x, const float* __restrict__ Wv, const float* __restrict__ bv) {
    mma_gemm<128, 128, 2, 4, false>(x, DMODEL, Wv, DMODEL, g_v, DMODEL,
                                    DMODEL, bv, 1.0f, blockIdx.y * 128, blockIdx.x * 128);
}

// scores = Q @ K^T / 8   (lower-triangular tiles only; B source is [n][k] => BNK path)
__global__ __launch_bounds__(256) void scores_kernel() {
    const int tj = blockIdx.x, ti = blockIdx.y;
    if (tj > ti) return;
    const int b = blockIdx.z;
    mma_gemm<128, 128, 2, 4, true>(
        g_q + (size_t)b * SEQ * DKEY, DKEY,
        g_k + (size_t)b * SEQ * DKEY, DKEY,
        g_p + (size_t)b * SEQ * SEQ, SEQ,
        DKEY, nullptr, 0.125f, ti * 128, tj * 128);
}

// O = P @ V with causal K bound (softmax zero-pads rows up to the tile boundary)
__global__ __launch_bounds__(256) void pv_kernel(float* __restrict__ O) {
    const int b = blockIdx.z;
    const int rowBase = blockIdx.y * 128;
    const int colBase = blockIdx.x * 128;
    mma_gemm<128, 128, 2, 4, false>(
        g_p + (size_t)b * SEQ * SEQ, SEQ,
        g_v + (size_t)b * SEQ * DMODEL, DMODEL,
        O + (size_t)b * SEQ * DMODEL, DMODEL,
        rowBase + 128, nullptr, 1.0f, rowBase, colBase);
}

// =================================================================================
// Row-wise causal softmax (unchanged from R3 baseline).
// Writes probs for j<=i and ZEROS for j in (i, round_up(i+1,128)).
// =================================================================================
__global__ __launch_bounds__(256) void softmax_kernel() {
    const int row = blockIdx.x;
    const int b   = row / SEQ;
    const int i   = row % SEQ;
    float* p = g_p + (size_t)b * SEQ * SEQ + (size_t)i * SEQ;

    const int L  = i + 1;
    const int Lp = ((i + 1 + 127) / 128) * 128;

    __shared__ float buf[SEQ];
    __shared__ float red[256];
    const int tid = threadIdx.x;

    float mx = -3.4e38f;
    for (int j = tid; j < L; j += 256) {
        float v = p[j];
        buf[j] = v;
        mx = fmaxf(mx, v);
    }
    red[tid] = mx;
    __syncthreads();
    for (int s = 128; s > 0; s >>= 1) {
        if (tid < s) red[tid] = fmaxf(red[tid], red[tid + s]);
        __syncthreads();
    }
    mx = red[0];
    __syncthreads();

    float sum = 0.0f;
    for (int j = tid; j < L; j += 256) {
        float e = __expf(buf[j] - mx);
        buf[j] = e;
        sum += e;
    }
    red[tid] = sum;
    __syncthreads();
    for (int s = 128; s > 0; s >>= 1) {
        if (tid < s) red[tid] += red[tid + s];
        __syncthreads();
    }
    const float inv = 1.0f / red[0];

    for (int j = tid; j < Lp; j += 256)
        p[j] = (j < L) ? buf[j] * inv : 0.0f;
}

// =================================================================================
// Launch: 6 graph-capturable kernel launches, no allocs, no syncs.
// Input order: input, Wq, bq, Wk, bk, Wv, bv
// =================================================================================
extern "C" void kernel_launch(void* const* d_in, const int* in_sizes, int n_in,
                              void* d_out, int out_size)
{
    const float* x  = (const float*)d_in[0];
    const float* Wq = (const float*)d_in[1];
    const float* bq = (const float*)d_in[2];
    const float* Wk = (const float*)d_in[3];
    const float* bk = (const float*)d_in[4];
    const float* Wv = (const float*)d_in[5];
    const float* bv = (const float*)d_in[6];
    float* out = (float*)d_out;

    proj_q_kernel<<<dim3(1, ROWS / 128), 256>>>(x, Wq, bq);
    proj_k_kernel<<<dim3(1, ROWS / 128), 256>>>(x, Wk, bk);
    proj_v_kernel<<<dim3(DMODEL / 128, ROWS / 128), 256>>>(x, Wv, bv);

    scores_kernel<<<dim3(SEQ / 128, SEQ / 128, NBATCH), 256>>>();

    softmax_kernel<<<NBATCH * SEQ, 256>>>();

    pv_kernel<<<dim3(DMODEL / 128, SEQ / 128, NBATCH), 256>>>(out);
}